// round 13
// baseline (speedup 1.0000x reference)
#include <cuda_runtime.h>
#include <cuda_fp16.h>
#include <cstdint>

#define BATCH 32
#define HDIM  56
#define WDIM  56
#define CIN   256
#define COUT  256
#define HP    58
#define WP    58
#define MTOT  (BATCH*HDIM*WDIM)        // 100352
#define NPIX_PAD (BATCH*HP*WP)         // 107648
#define NCHUNK 36                      // 9 taps * 4 chunks of 64 channels
#define NSTAGE 3

#define STAGE_BYTES 32768              // A 16KB | B 16KB

// padded activations, fp16: [pix][4 chunks][64ch * 2B] = 512B/pixel
__device__ __align__(1024) unsigned char g_apad[(size_t)NPIX_PAD * 512];
// packed weights fp16: [tap 9][chunk 4][co 256][64ch * 2B = 128B]
__device__ __align__(1024) unsigned char g_bpack[9*4*256*128];

// ---------------- prep kernels ----------------
// 2 pixels per 128-thread block; 64 threads x 4 channels = 256 channels each.
__global__ void prep_a_kernel(const float* __restrict__ in) {
    const int t   = threadIdx.x;
    const int pix = blockIdx.x * 2 + (t >> 6);
    const int tt  = t & 63;
    const int b   = pix / (HP*WP);
    const int rr  = pix % (HP*WP);
    const int yp  = rr / WP, xp = rr % WP;
    const int c0  = tt * 4;               // 0..252
    const int chunk = c0 >> 6, i = c0 & 63;
    unsigned long long hw = 0ull;
    if (!(yp == 0 || yp == HP-1 || xp == 0 || xp == WP-1)) {
        const float4 v = *(const float4*)(in +
            ((size_t)((b*HDIM + (yp-1))*WDIM + (xp-1)))*CIN + c0);
        const float vv[4] = {v.x, v.y, v.z, v.w};
        #pragma unroll
        for (int j = 0; j < 4; j++) {
            __half h = __float2half_rn(vv[j]);
            hw |= (unsigned long long)(*(unsigned short*)&h) << (16*j);
        }
    }
    *(unsigned long long*)(g_apad + (size_t)pix*512 + chunk*128 + i*2) = hw;
}

__global__ void prep_b_kernel(const float* __restrict__ wt) {
    const int k  = blockIdx.x;       // 0..2303 : (ky*3+kx)*256 + ci
    const int co = threadIdx.x;      // 0..255
    const float v = wt[(size_t)k*COUT + co];
    __half h = __float2half_rn(v);
    const int tap = k >> 8, ci = k & 255;
    const int chunk = ci >> 6, i = ci & 63;
    *(unsigned short*)(g_bpack + ((size_t)((tap*4 + chunk)*256 + co))*128 + i*2)
        = *(unsigned short*)&h;
}

// ---------------- device helpers ----------------
__device__ __forceinline__ uint32_t smem_u32(const void* p) {
    uint32_t a;
    asm("{ .reg .u64 t; cvta.to.shared.u64 t, %1; cvt.u32.u64 %0, t; }" : "=r"(a) : "l"(p));
    return a;
}

#define LDSM4(r0,r1,r2,r3,addr) \
    asm volatile("ldmatrix.sync.aligned.m8n8.x4.shared.b16 {%0,%1,%2,%3}, [%4];" \
        : "=r"(r0), "=r"(r1), "=r"(r2), "=r"(r3) : "r"(addr))

__device__ __forceinline__ void mma16816(float* c, const uint32_t* a, const uint32_t* b) {
    asm volatile(
        "mma.sync.aligned.m16n8k16.row.col.f32.f16.f16.f32 "
        "{%0,%1,%2,%3}, {%4,%5,%6,%7}, {%8,%9}, {%0,%1,%2,%3};"
        : "+f"(c[0]), "+f"(c[1]), "+f"(c[2]), "+f"(c[3])
        : "r"(a[0]), "r"(a[1]), "r"(a[2]), "r"(a[3]), "r"(b[0]), "r"(b[1]));
}

// ---------------- main conv kernel ----------------
// 128 threads = 4 warps in 2x2; warp tile 64x64; CTA tile 128x128.
__global__ void __launch_bounds__(128, 2) conv_mma_kernel(
    const float* __restrict__ bias, float* __restrict__ out)
{
    extern __shared__ unsigned char smem[];
    const uint32_t sb = smem_u32(smem);
    const int t = threadIdx.x;
    const int lane = t & 31, warp = t >> 5;
    const int bm = blockIdx.y * 128;
    const int bn = blockIdx.x * 128;
    const int m0 = (warp >> 1) * 64;     // 2 m-warps
    const int n0 = (warp & 1) * 64;      // 2 n-warps

    // ---- loader setup: every thread loads A row t AND B row t ----
    const int m  = bm + t;
    const int b  = m / (HDIM*WDIM);
    const int r2 = m % (HDIM*WDIM);
    const int y  = r2 / WDIM, x = r2 % WDIM;
    const unsigned char* gA = g_apad + (size_t)((b*HP + y)*WP + x) * 512;
    const unsigned char* gB = g_bpack + ((size_t)(bn + t)) * 128;
    const uint32_t swz = (uint32_t)((t & 7) << 4);

    auto load_chunk = [&](int c, int stg) {
        const int tap = c >> 2;
        const unsigned char* asrc = gA + (size_t)((tap/3)*WP + (tap%3))*512 + (c & 3)*128;
        const unsigned char* bsrc = gB + (size_t)c * (256*128);
        const uint32_t adst = sb + stg*STAGE_BYTES + (uint32_t)t*128;
        const uint32_t bdst = adst + 16384;
        #pragma unroll
        for (int j = 0; j < 8; j++) {
            const uint32_t o = ((uint32_t)(j*16)) ^ swz;
            asm volatile("cp.async.cg.shared.global [%0], [%1], 16;"
                         :: "r"(adst + o), "l"(asrc + j*16) : "memory");
            asm volatile("cp.async.cg.shared.global [%0], [%1], 16;"
                         :: "r"(bdst + o), "l"(bsrc + j*16) : "memory");
        }
        asm volatile("cp.async.commit_group;" ::: "memory");
    };

    // ---- ldmatrix lane addressing ----
    const uint32_t lr   = (uint32_t)(lane & 15);
    const uint32_t koff = (uint32_t)((lane >> 4) << 4);
    const uint32_t xorv = (uint32_t)((lane & 7) << 4);

    float acc[4][8][4];
    #pragma unroll
    for (int i = 0; i < 4; i++)
        #pragma unroll
        for (int j = 0; j < 8; j++)
            #pragma unroll
            for (int k = 0; k < 4; k++) acc[i][j][k] = 0.f;

    // prologue: 2 chunks in flight
    load_chunk(0, 0);
    load_chunk(1, 1);

    int stg = 0;        // stage of chunk c
    #pragma unroll 1
    for (int c = 0; c < NCHUNK; c++) {
        if (c == NCHUNK - 1)
            asm volatile("cp.async.wait_group 0;" ::: "memory");
        else
            asm volatile("cp.async.wait_group 1;" ::: "memory");
        __syncthreads();   // single barrier per chunk: also releases stage (c+2)%3,
                           // whose readers (chunk c-1) finished before this point.

        const uint32_t Ab = sb + stg*STAGE_BYTES;
        const uint32_t Bb = Ab + 16384;

        #pragma unroll
        for (int kh = 0; kh < 4; kh++) {
            uint32_t ah[4][4], bh[8][2];
            const uint32_t chi = (uint32_t)(kh*32) + koff;
            #pragma unroll
            for (int mi = 0; mi < 4; mi++) {
                const uint32_t r = Ab + (uint32_t)(m0 + mi*16 + lr)*128;
                LDSM4(ah[mi][0], ah[mi][1], ah[mi][2], ah[mi][3], r + (chi ^ xorv));
            }
            #pragma unroll
            for (int nb = 0; nb < 4; nb++) {
                const uint32_t r = Bb + (uint32_t)(n0 + nb*16 + lr)*128;
                uint32_t b0, b1, b2, b3;
                LDSM4(b0, b1, b2, b3, r + (chi ^ xorv));
                bh[nb*2][0] = b0; bh[nb*2][1] = b2;
                bh[nb*2+1][0] = b1; bh[nb*2+1][1] = b3;
            }
            #pragma unroll
            for (int mi = 0; mi < 4; mi++)
                #pragma unroll
                for (int ni = 0; ni < 8; ni++)
                    mma16816(acc[mi][ni], ah[mi], bh[ni]);

            // issue next-next chunk's loads after kh=0 compute is in flight
            if (kh == 0 && c + 2 < NCHUNK) {
                int ns = stg + 2; if (ns >= NSTAGE) ns -= NSTAGE;
                load_chunk(c + 2, ns);
            }
        }

        if (++stg == NSTAGE) stg = 0;
    }

    // ---- epilogue ----
    const int g = lane >> 2, q = lane & 3;
    #pragma unroll
    for (int ni = 0; ni < 8; ni++) {
        const int ncol = bn + n0 + ni*8 + q*2;
        const float2 bv = *(const float2*)(bias + ncol);
        #pragma unroll
        for (int mi = 0; mi < 4; mi++) {
            const int mrow = bm + m0 + mi*16 + g;
            float2 o0, o1;
            o0.x = acc[mi][ni][0] + bv.x; o0.y = acc[mi][ni][1] + bv.y;
            o1.x = acc[mi][ni][2] + bv.x; o1.y = acc[mi][ni][3] + bv.y;
            *(float2*)(out + (size_t)mrow*COUT + ncol)       = o0;
            *(float2*)(out + (size_t)(mrow+8)*COUT + ncol)   = o1;
        }
    }
}

// ---------------- launch ----------------
extern "C" void kernel_launch(void* const* d_in, const int* in_sizes, int n_in,
                              void* d_out, int out_size) {
    const float* in   = (const float*)d_in[0];   // [32,56,56,256] f32
    const float* wt   = (const float*)d_in[1];   // [3,3,256,256]  f32
    const float* bias = (const float*)d_in[2];   // [256]          f32
    float* out = (float*)d_out;

    static int smem_set = 0;
    if (!smem_set) {
        cudaFuncSetAttribute(conv_mma_kernel,
                             cudaFuncAttributeMaxDynamicSharedMemorySize, NSTAGE*STAGE_BYTES);
        smem_set = 1;
    }

    prep_a_kernel<<<NPIX_PAD/2, 128>>>(in);
    prep_b_kernel<<<9*256, 256>>>(wt);
    dim3 grid(2, MTOT/128);   // (2, 784)
    conv_mma_kernel<<<grid, 128, NSTAGE*STAGE_BYTES>>>(bias, out);
}

// round 14
// speedup vs baseline: 1.1465x; 1.1465x over previous
#include <cuda_runtime.h>
#include <cuda_fp16.h>
#include <cstdint>

#define BATCH 32
#define HDIM  56
#define WDIM  56
#define CIN   256
#define COUT  256
#define HP    58
#define WP    58
#define MTOT  (BATCH*HDIM*WDIM)        // 100352
#define NPIX_PAD (BATCH*HP*WP)         // 107648
#define NCHUNK 36                      // 9 taps * 4 chunks of 64 channels
#define NSTAGE 3

#define STAGE_BYTES 32768              // A 16KB | B 16KB

// padded activations, fp16: [pix][4 chunks][64ch * 2B] = 512B/pixel
__device__ __align__(1024) unsigned char g_apad[(size_t)NPIX_PAD * 512];
// packed weights fp16: [tap 9][chunk 4][co 256][64ch * 2B = 128B]
__device__ __align__(1024) unsigned char g_bpack[9*4*256*128];

// ---------------- prep kernels ----------------
// 2 pixels per 128-thread block; 64 threads x 4 channels = 256 channels each.
__global__ void prep_a_kernel(const float* __restrict__ in) {
    const int t   = threadIdx.x;
    const int pix = blockIdx.x * 2 + (t >> 6);
    const int tt  = t & 63;
    const int b   = pix / (HP*WP);
    const int rr  = pix % (HP*WP);
    const int yp  = rr / WP, xp = rr % WP;
    const int c0  = tt * 4;               // 0..252
    const int chunk = c0 >> 6, i = c0 & 63;
    unsigned long long hw = 0ull;
    if (!(yp == 0 || yp == HP-1 || xp == 0 || xp == WP-1)) {
        const float4 v = *(const float4*)(in +
            ((size_t)((b*HDIM + (yp-1))*WDIM + (xp-1)))*CIN + c0);
        const float vv[4] = {v.x, v.y, v.z, v.w};
        #pragma unroll
        for (int j = 0; j < 4; j++) {
            __half h = __float2half_rn(vv[j]);
            hw |= (unsigned long long)(*(unsigned short*)&h) << (16*j);
        }
    }
    *(unsigned long long*)(g_apad + (size_t)pix*512 + chunk*128 + i*2) = hw;
}

__global__ void prep_b_kernel(const float* __restrict__ wt) {
    const int k  = blockIdx.x;       // 0..2303 : (ky*3+kx)*256 + ci
    const int co = threadIdx.x;      // 0..255
    const float v = wt[(size_t)k*COUT + co];
    __half h = __float2half_rn(v);
    const int tap = k >> 8, ci = k & 255;
    const int chunk = ci >> 6, i = ci & 63;
    *(unsigned short*)(g_bpack + ((size_t)((tap*4 + chunk)*256 + co))*128 + i*2)
        = *(unsigned short*)&h;
}

// ---------------- device helpers ----------------
__device__ __forceinline__ uint32_t smem_u32(const void* p) {
    uint32_t a;
    asm("{ .reg .u64 t; cvta.to.shared.u64 t, %1; cvt.u32.u64 %0, t; }" : "=r"(a) : "l"(p));
    return a;
}

#define LDSM4(r0,r1,r2,r3,addr) \
    asm volatile("ldmatrix.sync.aligned.m8n8.x4.shared.b16 {%0,%1,%2,%3}, [%4];" \
        : "=r"(r0), "=r"(r1), "=r"(r2), "=r"(r3) : "r"(addr))

__device__ __forceinline__ void mma16816(float* c, const uint32_t* a, const uint32_t* b) {
    asm volatile(
        "mma.sync.aligned.m16n8k16.row.col.f32.f16.f16.f32 "
        "{%0,%1,%2,%3}, {%4,%5,%6,%7}, {%8,%9}, {%0,%1,%2,%3};"
        : "+f"(c[0]), "+f"(c[1]), "+f"(c[2]), "+f"(c[3])
        : "r"(a[0]), "r"(a[1]), "r"(a[2]), "r"(a[3]), "r"(b[0]), "r"(b[1]));
}

// ---------------- main conv kernel ----------------
// 128 threads = 4 warps in 2x2; warp tile 64x64; CTA tile 128x128.
// Fragment double-buffering: LDSM for kh+1 overlaps MMAs of kh.
__global__ void __launch_bounds__(128, 2) conv_mma_kernel(
    const float* __restrict__ bias, float* __restrict__ out)
{
    extern __shared__ unsigned char smem[];
    const uint32_t sb = smem_u32(smem);
    const int t = threadIdx.x;
    const int lane = t & 31, warp = t >> 5;
    const int bm = blockIdx.y * 128;
    const int bn = blockIdx.x * 128;
    const int m0 = (warp >> 1) * 64;     // 2 m-warps
    const int n0 = (warp & 1) * 64;      // 2 n-warps

    // ---- loader setup: every thread loads A row t AND B row t ----
    const int m  = bm + t;
    const int b  = m / (HDIM*WDIM);
    const int r2 = m % (HDIM*WDIM);
    const int y  = r2 / WDIM, x = r2 % WDIM;
    const unsigned char* gA = g_apad + (size_t)((b*HP + y)*WP + x) * 512;
    const unsigned char* gB = g_bpack + ((size_t)(bn + t)) * 128;
    const uint32_t swz = (uint32_t)((t & 7) << 4);

    auto load_chunk = [&](int c, int stg) {
        const int tap = c >> 2;
        const unsigned char* asrc = gA + (size_t)((tap/3)*WP + (tap%3))*512 + (c & 3)*128;
        const unsigned char* bsrc = gB + (size_t)c * (256*128);
        const uint32_t adst = sb + stg*STAGE_BYTES + (uint32_t)t*128;
        const uint32_t bdst = adst + 16384;
        #pragma unroll
        for (int j = 0; j < 8; j++) {
            const uint32_t o = ((uint32_t)(j*16)) ^ swz;
            asm volatile("cp.async.cg.shared.global [%0], [%1], 16;"
                         :: "r"(adst + o), "l"(asrc + j*16) : "memory");
            asm volatile("cp.async.cg.shared.global [%0], [%1], 16;"
                         :: "r"(bdst + o), "l"(bsrc + j*16) : "memory");
        }
        asm volatile("cp.async.commit_group;" ::: "memory");
    };

    // ---- ldmatrix lane addressing ----
    const uint32_t lr   = (uint32_t)(lane & 15);
    const uint32_t koff = (uint32_t)((lane >> 4) << 4);
    const uint32_t xorv = (uint32_t)((lane & 7) << 4);

    // fragment load for one kh slice into given buffers
    auto ldsm_slice = [&](uint32_t Ab, uint32_t Bb, int kh,
                          uint32_t (*ah)[4], uint32_t (*bh)[2]) {
        const uint32_t chi = (uint32_t)(kh*32) + koff;
        #pragma unroll
        for (int mi = 0; mi < 4; mi++) {
            const uint32_t r = Ab + (uint32_t)(m0 + mi*16 + lr)*128;
            LDSM4(ah[mi][0], ah[mi][1], ah[mi][2], ah[mi][3], r + (chi ^ xorv));
        }
        #pragma unroll
        for (int nb = 0; nb < 4; nb++) {
            const uint32_t r = Bb + (uint32_t)(n0 + nb*16 + lr)*128;
            uint32_t b0, b1, b2, b3;
            LDSM4(b0, b1, b2, b3, r + (chi ^ xorv));
            bh[nb*2][0] = b0; bh[nb*2][1] = b2;
            bh[nb*2+1][0] = b1; bh[nb*2+1][1] = b3;
        }
    };

    float acc[4][8][4];
    #pragma unroll
    for (int i = 0; i < 4; i++)
        #pragma unroll
        for (int j = 0; j < 8; j++)
            #pragma unroll
            for (int k = 0; k < 4; k++) acc[i][j][k] = 0.f;

    // prologue: 2 chunks in flight
    load_chunk(0, 0);
    load_chunk(1, 1);

    uint32_t ah[2][4][4], bh[2][8][2];

    int stg = 0;        // stage of chunk c
    #pragma unroll 1
    for (int c = 0; c < NCHUNK; c++) {
        if (c == NCHUNK - 1)
            asm volatile("cp.async.wait_group 0;" ::: "memory");
        else
            asm volatile("cp.async.wait_group 1;" ::: "memory");
        __syncthreads();   // single barrier per chunk: also releases stage (c+2)%3,
                           // whose readers (chunk c-1) finished before this point.

        const uint32_t Ab = sb + stg*STAGE_BYTES;
        const uint32_t Bb = Ab + 16384;

        // prefetch kh=0 fragments
        ldsm_slice(Ab, Bb, 0, ah[0], bh[0]);

        #pragma unroll
        for (int kh = 0; kh < 4; kh++) {
            const int cur = kh & 1, nxt = cur ^ 1;
            // prefetch next slice's fragments; independent of cur MMAs,
            // so LDSM latency hides under the tensor-pipe work below.
            if (kh < 3)
                ldsm_slice(Ab, Bb, kh + 1, ah[nxt], bh[nxt]);
            // issue next-next chunk's cp.async away from the kh=0/1 LDSM bursts
            if (kh == 2 && c + 2 < NCHUNK) {
                int ns = stg + 2; if (ns >= NSTAGE) ns -= NSTAGE;
                load_chunk(c + 2, ns);
            }
            #pragma unroll
            for (int mi = 0; mi < 4; mi++)
                #pragma unroll
                for (int ni = 0; ni < 8; ni++)
                    mma16816(acc[mi][ni], ah[cur][mi], bh[cur][ni]);
        }

        if (++stg == NSTAGE) stg = 0;
    }

    // ---- epilogue ----
    const int g = lane >> 2, q = lane & 3;
    #pragma unroll
    for (int ni = 0; ni < 8; ni++) {
        const int ncol = bn + n0 + ni*8 + q*2;
        const float2 bv = *(const float2*)(bias + ncol);
        #pragma unroll
        for (int mi = 0; mi < 4; mi++) {
            const int mrow = bm + m0 + mi*16 + g;
            float2 o0, o1;
            o0.x = acc[mi][ni][0] + bv.x; o0.y = acc[mi][ni][1] + bv.y;
            o1.x = acc[mi][ni][2] + bv.x; o1.y = acc[mi][ni][3] + bv.y;
            *(float2*)(out + (size_t)mrow*COUT + ncol)       = o0;
            *(float2*)(out + (size_t)(mrow+8)*COUT + ncol)   = o1;
        }
    }
}

// ---------------- launch ----------------
extern "C" void kernel_launch(void* const* d_in, const int* in_sizes, int n_in,
                              void* d_out, int out_size) {
    const float* in   = (const float*)d_in[0];   // [32,56,56,256] f32
    const float* wt   = (const float*)d_in[1];   // [3,3,256,256]  f32
    const float* bias = (const float*)d_in[2];   // [256]          f32
    float* out = (float*)d_out;

    static int smem_set = 0;
    if (!smem_set) {
        cudaFuncSetAttribute(conv_mma_kernel,
                             cudaFuncAttributeMaxDynamicSharedMemorySize, NSTAGE*STAGE_BYTES);
        smem_set = 1;
    }

    prep_a_kernel<<<NPIX_PAD/2, 128>>>(in);
    prep_b_kernel<<<9*256, 256>>>(wt);
    dim3 grid(2, MTOT/128);   // (2, 784)
    conv_mma_kernel<<<grid, 128, NSTAGE*STAGE_BYTES>>>(bias, out);
}